// round 15
// baseline (speedup 1.0000x reference)
#include <cuda_runtime.h>
#include <cuda_fp16.h>
#include <cstdint>
#include <math.h>

// ---------------------------------------------------------------------------
// FEMRMamba: 2-layer Mamba over 8 ragged subjects, compact [6848] layout.
// GEMMs: single-fp16 HMMA, 256x128 block / 64x32 warp, 4-stage cp.async.
// out_proj split-K=2 fused reduce+norm. Chunked scan (A/B/C); conv fused
// into scanA via rolling window (k_conv emits fp16 GEMM operand only).
// ---------------------------------------------------------------------------

#define TOTAL   6848
#define DM      768
#define DI      1536
#define DS      16
#define DTRANK  48
#define NSUBJ   8
#define EPS     1e-5f
#define CHUNK   64
#define MAXCH   16

__constant__ int c_off[NSUBJ] = {0, 1024, 1920, 2688, 3712, 4224, 4864, 5824};
__constant__ int c_len[NSUBJ] = {1024, 896, 768, 1024, 512, 640, 960, 1024};

// ---------------- scratch (device globals) ---------------------------------
__device__ float g_x  [TOTAL * DM];
__device__ float g_xz [TOTAL * 2 * DI];
__device__ float g_py [TOTAL * DI];          // scanA partial y
__device__ float g_dbl[TOTAL * 80];
__device__ float g_dblp[4 * TOTAL * 80];
__device__ float g_op  [2 * TOTAL * DM];     // out_proj split-K partials
__device__ float g_dtp[TOTAL * DI];          // dt_proj out; scanA -> cumsum S

__device__ float g_hend  [NSUBJ * MAXCH * DI * DS];
__device__ float g_hstart[NSUBJ * MAXCH * DI * DS];
__device__ float g_schunk[NSUBJ * MAXCH * DI];

__device__ __half g_hn_h[TOTAL * DM];
__device__ __half g_xs_h[TOTAL * DI];
__device__ __half g_db_h[TOTAL * 64];
__device__ __half g_y_h [TOTAL * DI];

__device__ __half g_w_ip[2 * 2 * DI * DM];
__device__ __half g_w_xp[2 * 80 * DI];
__device__ __half g_w_dt[2 * DI * 64];
__device__ __half g_w_op[2 * DM * DI];

// ---------------------------------------------------------------------------
__device__ __forceinline__ float warp_sum(float v) {
#pragma unroll
    for (int o = 16; o > 0; o >>= 1) v += __shfl_xor_sync(0xffffffffu, v, o);
    return v;
}
__device__ __forceinline__ uint32_t smem_u32(const void* p) {
    uint32_t a;
    asm("{ .reg .u64 t; cvta.to.shared.u64 t, %1; cvt.u32.u64 %0, t; }"
        : "=r"(a) : "l"(p));
    return a;
}
__device__ __forceinline__ void cp16(uint32_t dst, const void* src, int srcSize) {
    asm volatile("cp.async.cg.shared.global [%0], [%1], 16, %2;"
                 :: "r"(dst), "l"(src), "r"(srcSize) : "memory");
}
__device__ __forceinline__ void ldsm4(uint32_t& r0, uint32_t& r1, uint32_t& r2,
                                      uint32_t& r3, uint32_t addr) {
    asm volatile("ldmatrix.sync.aligned.m8n8.x4.shared.b16 {%0,%1,%2,%3}, [%4];"
                 : "=r"(r0), "=r"(r1), "=r"(r2), "=r"(r3) : "r"(addr));
}
__device__ __forceinline__ void mma16816(float* c, const uint32_t* a,
                                         const uint32_t* b) {
    asm volatile("mma.sync.aligned.m16n8k16.row.col.f32.f16.f16.f32 "
                 "{%0,%1,%2,%3}, {%4,%5,%6,%7}, {%8,%9}, {%0,%1,%2,%3};"
                 : "+f"(c[0]), "+f"(c[1]), "+f"(c[2]), "+f"(c[3])
                 : "r"(a[0]), "r"(a[1]), "r"(a[2]), "r"(a[3]),
                   "r"(b[0]), "r"(b[1]));
}

// ---------------------------------------------------------------------------
#define N_IP (2 * 2 * DI * DM)
#define N_XP (2 * 80 * DI)
#define N_OP (2 * DM * DI)
#define N_DT (2 * DI * 64)
#define N_CVT (N_IP + N_XP + N_OP + N_DT)

__global__ void k_cvt_all(const float* __restrict__ ip, const float* __restrict__ xp,
                          const float* __restrict__ dp, const float* __restrict__ op,
                          __half* __restrict__ wip, __half* __restrict__ wxp,
                          __half* __restrict__ wdt, __half* __restrict__ wop) {
    int idx = blockIdx.x * blockDim.x + threadIdx.x;
    if (idx < N_IP) { wip[idx] = __float2half(ip[idx]); return; }
    idx -= N_IP;
    if (idx < N_XP) { wxp[idx] = __float2half(xp[idx]); return; }
    idx -= N_XP;
    if (idx < N_OP) { wop[idx] = __float2half(op[idx]); return; }
    idx -= N_OP;
    if (idx < N_DT) {
        int r = idx >> 6, c = idx & 63;
        wdt[idx] = __float2half(c < 48 ? dp[r * 48 + c] : 0.f);
    }
}

// ---------------------------------------------------------------------------
__global__ void k_embed_norm(const int* __restrict__ tokens,
                             const float* __restrict__ embed,
                             const float* __restrict__ w,
                             const float* __restrict__ w0,
                             float* __restrict__ out,
                             __half* __restrict__ hn) {
    int row  = blockIdx.x * 8 + (threadIdx.x >> 5);
    int lane = threadIdx.x & 31;
    if (row >= TOTAL) return;
    int tok = tokens[row];
    const float4* e   = (const float4*)(embed + (size_t)tok * DM);
    const float4* w4  = (const float4*)w;
    const float4* w04 = (const float4*)w0;
    float4 v[6];
    float ss = 0.f;
#pragma unroll
    for (int i = 0; i < 6; i++) {
        v[i] = e[lane + 32 * i];
        ss += v[i].x * v[i].x + v[i].y * v[i].y + v[i].z * v[i].z + v[i].w * v[i].w;
    }
    ss = warp_sum(ss);
    float r = rsqrtf(ss * (1.f / DM) + EPS);
    float4* o4 = (float4*)(out + (size_t)row * DM);
    float ss2 = 0.f;
#pragma unroll
    for (int i = 0; i < 6; i++) {
        float4 wv = w4[lane + 32 * i];
        v[i].x *= r * wv.x; v[i].y *= r * wv.y;
        v[i].z *= r * wv.z; v[i].w *= r * wv.w;
        o4[lane + 32 * i] = v[i];
        ss2 += v[i].x * v[i].x + v[i].y * v[i].y + v[i].z * v[i].z + v[i].w * v[i].w;
    }
    ss2 = warp_sum(ss2);
    float r2 = rsqrtf(ss2 * (1.f / DM) + EPS);
    size_t base = (size_t)row * DM;
#pragma unroll
    for (int i = 0; i < 6; i++) {
        float4 wv = w04[lane + 32 * i];
        size_t c = base + (lane + 32 * i) * 4;
        hn[c + 0] = __float2half(v[i].x * r2 * wv.x);
        hn[c + 1] = __float2half(v[i].y * r2 * wv.y);
        hn[c + 2] = __float2half(v[i].z * r2 * wv.z);
        hn[c + 3] = __float2half(v[i].w * r2 * wv.w);
    }
}

// ---------------------------------------------------------------------------
__global__ void k_reduce_op_norm(const float* __restrict__ p,
                                 float* __restrict__ x,
                                 const float* __restrict__ w,
                                 __half* __restrict__ hn) {
    int row  = blockIdx.x * 8 + (threadIdx.x >> 5);
    int lane = threadIdx.x & 31;
    if (row >= TOTAL) return;
    const float4* p0 = (const float4*)(p + (size_t)row * DM);
    const float4* p1 = (const float4*)(p + (size_t)(TOTAL + row) * DM);
    float4* xp = (float4*)(x + (size_t)row * DM);
    const float4* w4 = (const float4*)w;
    float4 v[6];
    float ss = 0.f;
#pragma unroll
    for (int i = 0; i < 6; i++) {
        float4 a = p0[lane + 32 * i], b = p1[lane + 32 * i], o = xp[lane + 32 * i];
        o.x += a.x + b.x; o.y += a.y + b.y; o.z += a.z + b.z; o.w += a.w + b.w;
        xp[lane + 32 * i] = o;
        v[i] = o;
        ss += o.x * o.x + o.y * o.y + o.z * o.z + o.w * o.w;
    }
    ss = warp_sum(ss);
    float r = rsqrtf(ss * (1.f / DM) + EPS);
    size_t base = (size_t)row * DM;
#pragma unroll
    for (int i = 0; i < 6; i++) {
        float4 wv = w4[lane + 32 * i];
        size_t c = base + (lane + 32 * i) * 4;
        hn[c + 0] = __float2half(v[i].x * r * wv.x);
        hn[c + 1] = __float2half(v[i].y * r * wv.y);
        hn[c + 2] = __float2half(v[i].z * r * wv.z);
        hn[c + 3] = __float2half(v[i].w * r * wv.w);
    }
}

// ---------------------------------------------------------------------------
__global__ void k_final_fused(const float* __restrict__ p,
                              const float* __restrict__ x,
                              const float* __restrict__ wf,
                              const float* __restrict__ wo,
                              float* __restrict__ out) {
    int row  = blockIdx.x * 8 + (threadIdx.x >> 5);
    int lane = threadIdx.x & 31;
    if (row >= TOTAL) return;
    const float4* p0 = (const float4*)(p + (size_t)row * DM);
    const float4* p1 = (const float4*)(p + (size_t)(TOTAL + row) * DM);
    const float4* xp = (const float4*)(x + (size_t)row * DM);
    const float4* wf4 = (const float4*)wf;
    const float4* wo4 = (const float4*)wo;
    float4 v[6];
    float ss = 0.f;
#pragma unroll
    for (int i = 0; i < 6; i++) {
        float4 a = p0[lane + 32 * i], b = p1[lane + 32 * i], o = xp[lane + 32 * i];
        o.x += a.x + b.x; o.y += a.y + b.y; o.z += a.z + b.z; o.w += a.w + b.w;
        v[i] = o;
        ss += o.x * o.x + o.y * o.y + o.z * o.z + o.w * o.w;
    }
    ss = warp_sum(ss);
    float r1 = rsqrtf(ss * (1.f / DM) + EPS);
    float ss2 = 0.f;
#pragma unroll
    for (int i = 0; i < 6; i++) {
        float4 wv = wf4[lane + 32 * i];
        v[i].x *= r1 * wv.x; v[i].y *= r1 * wv.y;
        v[i].z *= r1 * wv.z; v[i].w *= r1 * wv.w;
        ss2 += v[i].x * v[i].x + v[i].y * v[i].y + v[i].z * v[i].z + v[i].w * v[i].w;
    }
    ss2 = warp_sum(ss2);
    float r2 = rsqrtf(ss2 * (1.f / DM) + EPS);
    float4* o4 = (float4*)(out + (size_t)row * DM);
#pragma unroll
    for (int i = 0; i < 6; i++) {
        float4 wv = wo4[lane + 32 * i];
        float4 t;
        t.x = v[i].x * r2 * wv.x; t.y = v[i].y * r2 * wv.y;
        t.z = v[i].z * r2 * wv.z; t.w = v[i].w * r2 * wv.w;
        o4[lane + 32 * i] = t;
    }
}

// ---------------------------------------------------------------------------
// fp16 HMMA GEMM-NT: block 256x128, BK=32, 512 thr, warp 64x32, 4-stage.
// ---------------------------------------------------------------------------
#define BK 32
#define LDS_ROW 40
#define TILE_A_B (256 * LDS_ROW * 2)
#define TILE_B_B (128 * LDS_ROW * 2)
#define STAGE_B  (TILE_A_B + TILE_B_B)
#define NSTAGE 4
#define GEMM_SMEM (NSTAGE * STAGE_B)      // 122880

__global__ __launch_bounds__(512, 1) void k_gemm(
    const __half* __restrict__ A, const __half* __restrict__ B,
    float* __restrict__ C, int M, int N, int Kpad, int ldc, int addRes,
    int splitk, size_t zStride) {
    extern __shared__ char smem[];
    const uint32_t sBase = smem_u32(smem);

    const int tid = threadIdx.x;
    const int bm = blockIdx.y * 256, bn = blockIdx.x * 128;
    const int wid = tid >> 5, lane = tid & 31;
    const int wm = wid & 3, wn = wid >> 2;

    const int per = (Kpad / BK) / splitk;
    const int kStart = blockIdx.z * per * BK;
    if (splitk > 1) C += blockIdx.z * zStride;

    float acc[4][4][4];
#pragma unroll
    for (int i = 0; i < 4; i++)
#pragma unroll
        for (int j = 0; j < 4; j++)
#pragma unroll
            for (int q = 0; q < 4; q++) acc[i][j][q] = 0.f;

    const int lrow = tid >> 2;
    const int lc = tid & 3;
    const int okA0 = (bm + lrow) < M ? 16 : 0;
    const int okA1 = (bm + lrow + 128) < M ? 16 : 0;
    const int okB  = (bn + lrow) < N ? 16 : 0;
    const size_t gA0 = (size_t)(bm + lrow) * Kpad + lc * 8;
    const size_t gA1 = gA0 + (size_t)128 * Kpad;
    const size_t gB  = (size_t)(bn + lrow) * Kpad + lc * 8;
    const uint32_t sA0 = (uint32_t)(lrow * LDS_ROW) * 2 + lc * 16;
    const uint32_t sA1 = sA0 + 128 * LDS_ROW * 2;
    const uint32_t sB  = TILE_A_B + sA0;

#define LOAD_STAGE(it, buf) do {                                               \
    int _kc = kStart + (it) * BK;                                              \
    uint32_t _d = sBase + (buf) * STAGE_B;                                     \
    cp16(_d + sA0, A + gA0 + _kc, okA0);                                       \
    cp16(_d + sA1, A + gA1 + _kc, okA1);                                       \
    cp16(_d + sB,  B + gB  + _kc, okB);                                        \
    asm volatile("cp.async.commit_group;" ::: "memory");                       \
} while (0)

    LOAD_STAGE(0, 0);
    if (per > 1) LOAD_STAGE(1, 1);
    if (per > 2) LOAD_STAGE(2, 2);

    const int aRow0 = wm * 64 + (lane & 15);
    const int aCol0 = (lane >> 4) << 3;
    const int bRow0 = wn * 32 + ((lane >> 4) << 3) + (lane & 7);
    const int bCol0 = ((lane >> 3) & 1) << 3;

    for (int it = 0; it < per; ++it) {
        int rem = per - 1 - it;
        if (rem >= 2)
            asm volatile("cp.async.wait_group 2;" ::: "memory");
        else if (rem == 1)
            asm volatile("cp.async.wait_group 1;" ::: "memory");
        else
            asm volatile("cp.async.wait_group 0;" ::: "memory");
        __syncthreads();
        if (it + 3 < per) LOAD_STAGE(it + 3, (it + 3) % NSTAGE);

        const uint32_t pA = sBase + (it % NSTAGE) * STAGE_B;
        const uint32_t pB = pA + TILE_A_B;

#pragma unroll
        for (int k16 = 0; k16 < 2; ++k16) {
            const int ac = k16 * 16 + aCol0;
            const int bc = k16 * 16 + bCol0;
            uint32_t af[4][4];
#pragma unroll
            for (int mt = 0; mt < 4; ++mt) {
                uint32_t off = (uint32_t)((aRow0 + mt * 16) * LDS_ROW + ac) * 2;
                ldsm4(af[mt][0], af[mt][1], af[mt][2], af[mt][3], pA + off);
            }
            uint32_t bf[2][4];
#pragma unroll
            for (int g = 0; g < 2; ++g) {
                uint32_t off = (uint32_t)((bRow0 + g * 16) * LDS_ROW + bc) * 2;
                ldsm4(bf[g][0], bf[g][1], bf[g][2], bf[g][3], pB + off);
            }
#pragma unroll
            for (int mt = 0; mt < 4; ++mt)
#pragma unroll
                for (int g = 0; g < 2; ++g) {
                    mma16816(acc[mt][2 * g],     af[mt], &bf[g][0]);
                    mma16816(acc[mt][2 * g + 1], af[mt], &bf[g][2]);
                }
        }
    }

#pragma unroll
    for (int mt = 0; mt < 4; ++mt) {
#pragma unroll
        for (int h = 0; h < 2; ++h) {
            int m = bm + wm * 64 + mt * 16 + (lane >> 2) + h * 8;
            if (m >= M) continue;
#pragma unroll
            for (int nt = 0; nt < 4; ++nt) {
                int n = bn + wn * 32 + nt * 8 + (lane & 3) * 2;
                if (n < N) {
                    float2 v = make_float2(acc[mt][nt][2 * h], acc[mt][nt][2 * h + 1]);
                    float* cp = C + (size_t)m * ldc + n;
                    if (addRes) { float2 o = *(float2*)cp; v.x += o.x; v.y += o.y; }
                    *(float2*)cp = v;
                }
            }
        }
    }
#undef LOAD_STAGE
}

// ---------------------------------------------------------------------------
__global__ void k_reduce4(const float* __restrict__ p, float* __restrict__ out,
                          __half* __restrict__ dbh) {
    int idx = blockIdx.x * blockDim.x + threadIdx.x;
    if (idx >= TOTAL * 80) return;
    const size_t s = (size_t)TOTAL * 80;
    float v = (p[idx] + p[idx + s]) + (p[idx + 2 * s] + p[idx + 3 * s]);
    out[idx] = v;
    int row = idx / 80, col = idx - row * 80;
    if (col < 48) {
        dbh[(size_t)row * 64 + col] = __float2half(v);
    } else if (col < 64) {
        dbh[(size_t)row * 64 + col] = __float2half(0.f);
    }
}

// ---------------------------------------------------------------------------
// conv+silu -> fp16 only (x_proj GEMM A operand)
// ---------------------------------------------------------------------------
__global__ void k_conv(const float* __restrict__ xz,
                       const float* __restrict__ cw,
                       const float* __restrict__ cb,
                       __half* __restrict__ xh) {
    int idx = blockIdx.x * blockDim.x + threadIdx.x;
    if (idx >= TOTAL * DI) return;
    int row = idx / DI;
    int d = idx - row * DI;
    int b = 0;
#pragma unroll
    for (int i = 1; i < NSUBJ; i++) if (row >= c_off[i]) b = i;
    int l = row - c_off[b];
    float acc = cb[d];
#pragma unroll
    for (int j = 0; j < 4; j++) {
        int ll = l - 3 + j;
        if (ll >= 0)
            acc = fmaf(cw[d * 4 + j], xz[(size_t)(row - 3 + j) * (2 * DI) + d], acc);
    }
    float v = acc * __frcp_rn(1.f + __expf(-acc));
    xh[idx] = __float2half(v);
}

// ---------------------------------------------------------------------------
// Chunked scan pass A: recomputes conv+silu via rolling window over xz.
// Writes partial y -> py, cumsum S -> dtp (in-place), chunk summaries.
// ---------------------------------------------------------------------------
__global__ __launch_bounds__(128) void k_scanA(
    float* __restrict__ dtp, const float* __restrict__ xz,
    float* __restrict__ py, const float* __restrict__ dbl,
    float* __restrict__ hend, float* __restrict__ schunk,
    const float* __restrict__ cw, const float* __restrict__ cb,
    const float* __restrict__ dtb, const float* __restrict__ alog,
    const float* __restrict__ Dp) {
    int bx = blockIdx.x;
    int s = bx / (MAXCH * 12);
    int rem = bx - s * (MAXCH * 12);
    int c = rem / 12;
    int d = (rem - c * 12) * 128 + threadIdx.x;
    int len = c_len[s];
    int t0 = c * CHUNK;
    if (t0 >= len) return;
    int tend = min(t0 + CHUNK, len);
    int off = c_off[s];

    float a[DS], st[DS];
    bool fast = true;
#pragma unroll
    for (int n = 0; n < DS; n++) {
        a[n] = -expf(alog[d * DS + n]);
        st[n] = 0.f;
        fast &= (fabsf(a[n] + (float)(n + 1)) <= 1e-5f * (float)(n + 1));
    }
    float bias = dtb[d], Dd = Dp[d];
    float cw0 = cw[d * 4 + 0], cw1 = cw[d * 4 + 1];
    float cw2 = cw[d * 4 + 2], cw3 = cw[d * 4 + 3];
    float cbd = cb[d];
    float S = 0.f;

    float w0 = (t0 >= 3) ? xz[(size_t)(off + t0 - 3) * (2 * DI) + d] : 0.f;
    float w1 = (t0 >= 2) ? xz[(size_t)(off + t0 - 2) * (2 * DI) + d] : 0.f;
    float w2 = (t0 >= 1) ? xz[(size_t)(off + t0 - 1) * (2 * DI) + d] : 0.f;

    for (int t = t0; t < tend; t++) {
        size_t idx = (size_t)(off + t) * DI + d;
        float w3 = xz[(size_t)(off + t) * (2 * DI) + d];
        float accv = cbd;
        accv = fmaf(cw0, w0, accv);
        accv = fmaf(cw1, w1, accv);
        accv = fmaf(cw2, w2, accv);
        accv = fmaf(cw3, w3, accv);
        float xt = accv * __frcp_rn(1.f + __expf(-accv));
        w0 = w1; w1 = w2; w2 = w3;

        float dtr = dtp[idx] + bias;
        float dt, p;
        if (dtr > 15.f) { dt = dtr; p = __expf(-dtr); }
        else {
            float e = __expf(dtr);
            p = __frcp_rn(1.f + e);
            dt = __logf(1.f + e);
        }
        S += dt;
        dtp[idx] = S;
        const float4* bc = (const float4*)(dbl + (size_t)(off + t) * 80 + DTRANK);
        float Bv[DS], Cv[DS];
        *(float4*)&Bv[0]  = bc[0]; *(float4*)&Bv[4]  = bc[1];
        *(float4*)&Bv[8]  = bc[2]; *(float4*)&Bv[12] = bc[3];
        *(float4*)&Cv[0]  = bc[4]; *(float4*)&Cv[4]  = bc[5];
        *(float4*)&Cv[8]  = bc[6]; *(float4*)&Cv[12] = bc[7];
        float u = dt * xt;
        float y = 0.f;
        if (fast) {
            float dA = 1.f;
#pragma unroll
            for (int n = 0; n < DS; n++) {
                dA *= p;
                st[n] = fmaf(dA, st[n], u * Bv[n]);
                y = fmaf(st[n], Cv[n], y);
            }
        } else {
#pragma unroll
            for (int n = 0; n < DS; n++) {
                float dA = __expf(dt * a[n]);
                st[n] = fmaf(dA, st[n], u * Bv[n]);
                y = fmaf(st[n], Cv[n], y);
            }
        }
        py[idx] = y + xt * Dd;
    }

    size_t hb = ((size_t)(s * MAXCH + c) * DI + d) * DS;
    float4* hp = (float4*)(hend + hb);
    hp[0] = *(float4*)&st[0];  hp[1] = *(float4*)&st[4];
    hp[2] = *(float4*)&st[8];  hp[3] = *(float4*)&st[12];
    schunk[(size_t)(s * MAXCH + c) * DI + d] = S;
}

// ---------------------------------------------------------------------------
// pass B: compose chunk boundary states once per (subject, d)
// ---------------------------------------------------------------------------
__global__ __launch_bounds__(128) void k_scanB(
    const float* __restrict__ hend, const float* __restrict__ schunk,
    float* __restrict__ hstart, const float* __restrict__ alog) {
    int bx = blockIdx.x;
    int s = bx / 12;
    int d = (bx - s * 12) * 128 + threadIdx.x;
    int nch = (c_len[s] + CHUNK - 1) / CHUNK;

    float a[DS], h[DS];
#pragma unroll
    for (int n = 0; n < DS; n++) {
        a[n] = -expf(alog[d * DS + n]);
        h[n] = 0.f;
    }

    for (int c = 0; c < nch; c++) {
        size_t hb = ((size_t)(s * MAXCH + c) * DI + d) * DS;
        float4* hs = (float4*)(hstart + hb);
        hs[0] = *(float4*)&h[0];  hs[1] = *(float4*)&h[4];
        hs[2] = *(float4*)&h[8];  hs[3] = *(float4*)&h[12];
        float Sc = schunk[(size_t)(s * MAXCH + c) * DI + d];
        const float4* he = (const float4*)(hend + hb);
        float e[DS];
        *(float4*)&e[0] = he[0];  *(float4*)&e[4]  = he[1];
        *(float4*)&e[8] = he[2];  *(float4*)&e[12] = he[3];
#pragma unroll
        for (int n = 0; n < DS; n++)
            h[n] = fmaf(__expf(Sc * a[n]), h[n], e[n]);
    }
}

// ---------------------------------------------------------------------------
// pass C: correct partial y with chunk-start state, gate, store y fp16
// ---------------------------------------------------------------------------
__global__ __launch_bounds__(128) void k_scanC(
    const float* __restrict__ dtp, const float* __restrict__ py,
    const float* __restrict__ dbl, const float* __restrict__ xz,
    const float* __restrict__ hstart,
    __half* __restrict__ yh,
    const float* __restrict__ alog) {
    int bx = blockIdx.x;
    int s = bx / (MAXCH * 12);
    int rem = bx - s * (MAXCH * 12);
    int c = rem / 12;
    int d = (rem - c * 12) * 128 + threadIdx.x;
    int len = c_len[s];
    int t0 = c * CHUNK;
    if (t0 >= len) return;
    int tend = min(t0 + CHUNK, len);
    int off = c_off[s];

    float a[DS], h0[DS];
    bool fast = true;
#pragma unroll
    for (int n = 0; n < DS; n++) {
        a[n] = -expf(alog[d * DS + n]);
        fast &= (fabsf(a[n] + (float)(n + 1)) <= 1e-5f * (float)(n + 1));
    }
    size_t hb = ((size_t)(s * MAXCH + c) * DI + d) * DS;
    const float4* hs = (const float4*)(hstart + hb);
    *(float4*)&h0[0] = hs[0];  *(float4*)&h0[4]  = hs[1];
    *(float4*)&h0[8] = hs[2];  *(float4*)&h0[12] = hs[3];

    for (int t = t0; t < tend; t++) {
        size_t idx = (size_t)(off + t) * DI + d;
        float S = dtp[idx];
        float y = py[idx];
        const float4* bc = (const float4*)(dbl + (size_t)(off + t) * 80 + DTRANK + DS);
        float Cv[DS];
        *(float4*)&Cv[0] = bc[0];  *(float4*)&Cv[4]  = bc[1];
        *(float4*)&Cv[8] = bc[2];  *(float4*)&Cv[12] = bc[3];
        if (fast) {
            float q = __expf(-S);
            float w = 1.f;
#pragma unroll
            for (int n = 0; n < DS; n++) {
                w *= q;
                y = fmaf(w * h0[n], Cv[n], y);
            }
        } else {
#pragma unroll
            for (int n = 0; n < DS; n++)
                y = fmaf(__expf(S * a[n]) * h0[n], Cv[n], y);
        }
        float z = xz[(size_t)(off + t) * (2 * DI) + DI + d];
        float sig = __frcp_rn(1.f + __expf(-z));
        yh[idx] = __float2half(y * (z * sig));
    }
}

// ---------------------------------------------------------------------------
extern "C" void kernel_launch(void* const* d_in, const int* in_sizes, int n_in,
                              void* d_out, int out_size) {
    const int*   tokens     = (const int*)d_in[0];
    const float* embed      = (const float*)d_in[1];
    const float* in_norm_w  = (const float*)d_in[2];
    const float* out_norm_w = (const float*)d_in[3];
    const float* norm_w     = (const float*)d_in[4];
    const float* in_proj_w  = (const float*)d_in[5];
    const float* conv_w     = (const float*)d_in[6];
    const float* conv_b     = (const float*)d_in[7];
    const float* x_proj_w   = (const float*)d_in[8];
    const float* dt_proj_w  = (const float*)d_in[9];
    const float* dt_proj_b  = (const float*)d_in[10];
    const float* A_log      = (const float*)d_in[11];
    const float* D_param    = (const float*)d_in[12];
    const float* out_proj_w = (const float*)d_in[13];
    const float* norm_f_w   = (const float*)d_in[14];
    float* out = (float*)d_out;

    float *p_x, *p_xz, *p_py, *p_dbl, *p_dblp, *p_op, *p_dtp, *p_he, *p_hs, *p_sc;
    __half *p_hn, *p_xsh, *p_dbh, *p_yh, *p_wip, *p_wxp, *p_wdt, *p_wop;
    cudaGetSymbolAddress((void**)&p_x,    g_x);
    cudaGetSymbolAddress((void**)&p_xz,   g_xz);
    cudaGetSymbolAddress((void**)&p_py,   g_py);
    cudaGetSymbolAddress((void**)&p_dbl,  g_dbl);
    cudaGetSymbolAddress((void**)&p_dblp, g_dblp);
    cudaGetSymbolAddress((void**)&p_op,   g_op);
    cudaGetSymbolAddress((void**)&p_dtp,  g_dtp);
    cudaGetSymbolAddress((void**)&p_he,   g_hend);
    cudaGetSymbolAddress((void**)&p_hs,   g_hstart);
    cudaGetSymbolAddress((void**)&p_sc,   g_schunk);
    cudaGetSymbolAddress((void**)&p_hn,   g_hn_h);
    cudaGetSymbolAddress((void**)&p_xsh,  g_xs_h);
    cudaGetSymbolAddress((void**)&p_dbh,  g_db_h);
    cudaGetSymbolAddress((void**)&p_yh,   g_y_h);
    cudaGetSymbolAddress((void**)&p_wip,  g_w_ip);
    cudaGetSymbolAddress((void**)&p_wxp,  g_w_xp);
    cudaGetSymbolAddress((void**)&p_wdt,  g_w_dt);
    cudaGetSymbolAddress((void**)&p_wop,  g_w_op);

    cudaFuncSetAttribute(k_gemm, cudaFuncAttributeMaxDynamicSharedMemorySize, GEMM_SMEM);

    const int rowBlocks = (TOTAL + 7) / 8;
    const int gy = (TOTAL + 255) / 256;          // 27
    const int scanBlocks = NSUBJ * MAXCH * 12;   // 1536

    k_cvt_all<<<(N_CVT + 255) / 256, 256>>>(in_proj_w, x_proj_w, dt_proj_w,
                                            out_proj_w, p_wip, p_wxp, p_wdt, p_wop);
    k_embed_norm<<<rowBlocks, 256>>>(tokens, embed, in_norm_w, norm_w, p_x, p_hn);

    for (int l = 0; l < 2; l++) {
        const float* cw   = conv_w    + (size_t)l * DI * 4;
        const float* cb   = conv_b    + (size_t)l * DI;
        const float* dpb  = dt_proj_b + (size_t)l * DI;
        const float* al   = A_log     + (size_t)l * DI * DS;
        const float* Dpar = D_param   + (size_t)l * DI;
        const __half* wip = p_wip + (size_t)l * 2 * DI * DM;
        const __half* wxp = p_wxp + (size_t)l * 80 * DI;
        const __half* wdt = p_wdt + (size_t)l * DI * 64;
        const __half* wop = p_wop + (size_t)l * DM * DI;

        // xz = hn @ in_proj^T : [TOTAL, 3072]
        k_gemm<<<dim3(2 * DI / 128, gy, 1), 512, GEMM_SMEM>>>(
            p_hn, wip, p_xz, TOTAL, 2 * DI, DM, 2 * DI, 0, 1, 0);

        // xs_h = fp16(silu(conv(x)+b)) — GEMM operand only
        k_conv<<<(TOTAL * DI + 255) / 256, 256>>>(p_xz, cw, cb, p_xsh);

        // dbl = xs @ x_proj^T : [TOTAL, 80] (split-K 4)
        k_gemm<<<dim3(1, gy, 4), 512, GEMM_SMEM>>>(
            p_xsh, wxp, p_dblp, TOTAL, 80, DI, 80, 0, 4, (size_t)TOTAL * 80);
        k_reduce4<<<(TOTAL * 80 + 255) / 256, 256>>>(p_dblp, p_dbl, p_dbh);

        // dtp = dbl[:, :48] @ dt_proj^T : [TOTAL, 1536] (Kpad=64)
        k_gemm<<<dim3(DI / 128, gy, 1), 512, GEMM_SMEM>>>(
            p_dbh, wdt, p_dtp, TOTAL, DI, 64, DI, 0, 1, 0);

        // chunked selective scan (conv recomputed in scanA; scanB composes)
        k_scanA<<<scanBlocks, 128>>>(p_dtp, p_xz, p_py, p_dbl, p_he, p_sc,
                                     cw, cb, dpb, al, Dpar);
        k_scanB<<<NSUBJ * 12, 128>>>(p_he, p_sc, p_hs, al);
        k_scanC<<<scanBlocks, 128>>>(p_dtp, p_py, p_dbl, p_xz, p_hs, p_yh, al);

        // out_proj split-K=2 -> partials
        k_gemm<<<dim3(DM / 128, gy, 2), 512, GEMM_SMEM>>>(
            p_yh, wop, p_op, TOTAL, DM, DI, DM, 0, 2, (size_t)TOTAL * DM);

        if (l == 0) {
            k_reduce_op_norm<<<rowBlocks, 256>>>(p_op, p_x, norm_w + DM, p_hn);
        } else {
            k_final_fused<<<rowBlocks, 256>>>(p_op, p_x, norm_f_w, out_norm_w, out);
        }
    }
}

// round 17
// speedup vs baseline: 1.0838x; 1.0838x over previous
#include <cuda_runtime.h>
#include <cuda_fp16.h>
#include <cstdint>
#include <math.h>

// ---------------------------------------------------------------------------
// FEMRMamba: 2-layer Mamba over 8 ragged subjects, compact [6848] layout.
// R13 configuration (best measured) + vectorized weight conversion.
// GEMMs: single-fp16 HMMA, 256x128 block / 64x32 warp, 4-stage cp.async.
// out_proj split-K=2 with reduce fused into following row-norm kernel.
// Scan: chunked parallel scan (A/B/C), cheap softplus.
// ---------------------------------------------------------------------------

#define TOTAL   6848
#define DM      768
#define DI      1536
#define DS      16
#define DTRANK  48
#define NSUBJ   8
#define EPS     1e-5f
#define CHUNK   64
#define MAXCH   16

__constant__ int c_off[NSUBJ] = {0, 1024, 1920, 2688, 3712, 4224, 4864, 5824};
__constant__ int c_len[NSUBJ] = {1024, 896, 768, 1024, 512, 640, 960, 1024};

// ---------------- scratch (device globals) ---------------------------------
__device__ float g_x  [TOTAL * DM];
__device__ float g_xz [TOTAL * 2 * DI];
__device__ float g_xs [TOTAL * DI];          // silu(conv); scanA -> partial y
__device__ float g_dbl[TOTAL * 80];
__device__ float g_dblp[4 * TOTAL * 80];
__device__ float g_op  [2 * TOTAL * DM];     // out_proj split-K partials
__device__ float g_dtp[TOTAL * DI];          // dt_proj out; scanA -> cumsum S

__device__ float g_hend  [NSUBJ * MAXCH * DI * DS];
__device__ float g_hstart[NSUBJ * MAXCH * DI * DS];
__device__ float g_schunk[NSUBJ * MAXCH * DI];

__device__ __half g_hn_h[TOTAL * DM];
__device__ __half g_xs_h[TOTAL * DI];
__device__ __half g_db_h[TOTAL * 64];
__device__ __half g_y_h [TOTAL * DI];

__device__ __half g_w_ip[2 * 2 * DI * DM];
__device__ __half g_w_xp[2 * 80 * DI];
__device__ __half g_w_dt[2 * DI * 64];
__device__ __half g_w_op[2 * DM * DI];

// ---------------------------------------------------------------------------
__device__ __forceinline__ float warp_sum(float v) {
#pragma unroll
    for (int o = 16; o > 0; o >>= 1) v += __shfl_xor_sync(0xffffffffu, v, o);
    return v;
}
__device__ __forceinline__ uint32_t smem_u32(const void* p) {
    uint32_t a;
    asm("{ .reg .u64 t; cvta.to.shared.u64 t, %1; cvt.u32.u64 %0, t; }"
        : "=r"(a) : "l"(p));
    return a;
}
__device__ __forceinline__ void cp16(uint32_t dst, const void* src, int srcSize) {
    asm volatile("cp.async.cg.shared.global [%0], [%1], 16, %2;"
                 :: "r"(dst), "l"(src), "r"(srcSize) : "memory");
}
__device__ __forceinline__ void ldsm4(uint32_t& r0, uint32_t& r1, uint32_t& r2,
                                      uint32_t& r3, uint32_t addr) {
    asm volatile("ldmatrix.sync.aligned.m8n8.x4.shared.b16 {%0,%1,%2,%3}, [%4];"
                 : "=r"(r0), "=r"(r1), "=r"(r2), "=r"(r3) : "r"(addr));
}
__device__ __forceinline__ void mma16816(float* c, const uint32_t* a,
                                         const uint32_t* b) {
    asm volatile("mma.sync.aligned.m16n8k16.row.col.f32.f16.f16.f32 "
                 "{%0,%1,%2,%3}, {%4,%5,%6,%7}, {%8,%9}, {%0,%1,%2,%3};"
                 : "+f"(c[0]), "+f"(c[1]), "+f"(c[2]), "+f"(c[3])
                 : "r"(a[0]), "r"(a[1]), "r"(a[2]), "r"(a[3]),
                   "r"(b[0]), "r"(b[1]));
}
__device__ __forceinline__ void cvt4(const float* __restrict__ s,
                                     __half* __restrict__ d) {
    float4 v = *(const float4*)s;
    __half2* d2 = (__half2*)d;
    d2[0] = __floats2half2_rn(v.x, v.y);
    d2[1] = __floats2half2_rn(v.z, v.w);
}

// ---------------------------------------------------------------------------
// one-shot weight conversion, 4 elements per thread (all regions 4-divisible)
// ---------------------------------------------------------------------------
#define N_IP (2 * 2 * DI * DM)
#define N_XP (2 * 80 * DI)
#define N_OP (2 * DM * DI)
#define N_DT (2 * DI * 64)
#define V_IP (N_IP / 4)
#define V_XP (N_XP / 4)
#define V_OP (N_OP / 4)
#define V_DT (N_DT / 4)
#define V_CVT (V_IP + V_XP + V_OP + V_DT)

__global__ void k_cvt_all(const float* __restrict__ ip, const float* __restrict__ xp,
                          const float* __restrict__ dp, const float* __restrict__ op,
                          __half* __restrict__ wip, __half* __restrict__ wxp,
                          __half* __restrict__ wdt, __half* __restrict__ wop) {
    int v = blockIdx.x * blockDim.x + threadIdx.x;
    if (v < V_IP) { cvt4(ip + 4 * v, wip + 4 * v); return; }
    v -= V_IP;
    if (v < V_XP) { cvt4(xp + 4 * v, wxp + 4 * v); return; }
    v -= V_XP;
    if (v < V_OP) { cvt4(op + 4 * v, wop + 4 * v); return; }
    v -= V_OP;
    if (v < V_DT) {
        int idx = 4 * v;
        int r = idx >> 6, c = idx & 63;     // c is 4-aligned; 48 boundary exact
        if (c < 48) {
            cvt4(dp + r * 48 + c, wdt + idx);
        } else {
            __half2 z = __floats2half2_rn(0.f, 0.f);
            __half2* d2 = (__half2*)(wdt + idx);
            d2[0] = z; d2[1] = z;
        }
    }
}

// ---------------------------------------------------------------------------
// embed gather + rmsnorm(in_norm) -> h fp32, and rmsnorm(norm_w[0]) -> hn fp16
// ---------------------------------------------------------------------------
__global__ void k_embed_norm(const int* __restrict__ tokens,
                             const float* __restrict__ embed,
                             const float* __restrict__ w,
                             const float* __restrict__ w0,
                             float* __restrict__ out,
                             __half* __restrict__ hn) {
    int row  = blockIdx.x * 8 + (threadIdx.x >> 5);
    int lane = threadIdx.x & 31;
    if (row >= TOTAL) return;
    int tok = tokens[row];
    const float4* e   = (const float4*)(embed + (size_t)tok * DM);
    const float4* w4  = (const float4*)w;
    const float4* w04 = (const float4*)w0;
    float4 v[6];
    float ss = 0.f;
#pragma unroll
    for (int i = 0; i < 6; i++) {
        v[i] = e[lane + 32 * i];
        ss += v[i].x * v[i].x + v[i].y * v[i].y + v[i].z * v[i].z + v[i].w * v[i].w;
    }
    ss = warp_sum(ss);
    float r = rsqrtf(ss * (1.f / DM) + EPS);
    float4* o4 = (float4*)(out + (size_t)row * DM);
    float ss2 = 0.f;
#pragma unroll
    for (int i = 0; i < 6; i++) {
        float4 wv = w4[lane + 32 * i];
        v[i].x *= r * wv.x; v[i].y *= r * wv.y;
        v[i].z *= r * wv.z; v[i].w *= r * wv.w;
        o4[lane + 32 * i] = v[i];
        ss2 += v[i].x * v[i].x + v[i].y * v[i].y + v[i].z * v[i].z + v[i].w * v[i].w;
    }
    ss2 = warp_sum(ss2);
    float r2 = rsqrtf(ss2 * (1.f / DM) + EPS);
    size_t base = (size_t)row * DM;
#pragma unroll
    for (int i = 0; i < 6; i++) {
        float4 wv = w04[lane + 32 * i];
        size_t c = base + (lane + 32 * i) * 4;
        hn[c + 0] = __float2half(v[i].x * r2 * wv.x);
        hn[c + 1] = __float2half(v[i].y * r2 * wv.y);
        hn[c + 2] = __float2half(v[i].z * r2 * wv.z);
        hn[c + 3] = __float2half(v[i].w * r2 * wv.w);
    }
}

// ---------------------------------------------------------------------------
__global__ void k_reduce_op_norm(const float* __restrict__ p,
                                 float* __restrict__ x,
                                 const float* __restrict__ w,
                                 __half* __restrict__ hn) {
    int row  = blockIdx.x * 8 + (threadIdx.x >> 5);
    int lane = threadIdx.x & 31;
    if (row >= TOTAL) return;
    const float4* p0 = (const float4*)(p + (size_t)row * DM);
    const float4* p1 = (const float4*)(p + (size_t)(TOTAL + row) * DM);
    float4* xp = (float4*)(x + (size_t)row * DM);
    const float4* w4 = (const float4*)w;
    float4 v[6];
    float ss = 0.f;
#pragma unroll
    for (int i = 0; i < 6; i++) {
        float4 a = p0[lane + 32 * i], b = p1[lane + 32 * i], o = xp[lane + 32 * i];
        o.x += a.x + b.x; o.y += a.y + b.y; o.z += a.z + b.z; o.w += a.w + b.w;
        xp[lane + 32 * i] = o;
        v[i] = o;
        ss += o.x * o.x + o.y * o.y + o.z * o.z + o.w * o.w;
    }
    ss = warp_sum(ss);
    float r = rsqrtf(ss * (1.f / DM) + EPS);
    size_t base = (size_t)row * DM;
#pragma unroll
    for (int i = 0; i < 6; i++) {
        float4 wv = w4[lane + 32 * i];
        size_t c = base + (lane + 32 * i) * 4;
        hn[c + 0] = __float2half(v[i].x * r * wv.x);
        hn[c + 1] = __float2half(v[i].y * r * wv.y);
        hn[c + 2] = __float2half(v[i].z * r * wv.z);
        hn[c + 3] = __float2half(v[i].w * r * wv.w);
    }
}

// ---------------------------------------------------------------------------
__global__ void k_final_fused(const float* __restrict__ p,
                              const float* __restrict__ x,
                              const float* __restrict__ wf,
                              const float* __restrict__ wo,
                              float* __restrict__ out) {
    int row  = blockIdx.x * 8 + (threadIdx.x >> 5);
    int lane = threadIdx.x & 31;
    if (row >= TOTAL) return;
    const float4* p0 = (const float4*)(p + (size_t)row * DM);
    const float4* p1 = (const float4*)(p + (size_t)(TOTAL + row) * DM);
    const float4* xp = (const float4*)(x + (size_t)row * DM);
    const float4* wf4 = (const float4*)wf;
    const float4* wo4 = (const float4*)wo;
    float4 v[6];
    float ss = 0.f;
#pragma unroll
    for (int i = 0; i < 6; i++) {
        float4 a = p0[lane + 32 * i], b = p1[lane + 32 * i], o = xp[lane + 32 * i];
        o.x += a.x + b.x; o.y += a.y + b.y; o.z += a.z + b.z; o.w += a.w + b.w;
        v[i] = o;
        ss += o.x * o.x + o.y * o.y + o.z * o.z + o.w * o.w;
    }
    ss = warp_sum(ss);
    float r1 = rsqrtf(ss * (1.f / DM) + EPS);
    float ss2 = 0.f;
#pragma unroll
    for (int i = 0; i < 6; i++) {
        float4 wv = wf4[lane + 32 * i];
        v[i].x *= r1 * wv.x; v[i].y *= r1 * wv.y;
        v[i].z *= r1 * wv.z; v[i].w *= r1 * wv.w;
        ss2 += v[i].x * v[i].x + v[i].y * v[i].y + v[i].z * v[i].z + v[i].w * v[i].w;
    }
    ss2 = warp_sum(ss2);
    float r2 = rsqrtf(ss2 * (1.f / DM) + EPS);
    float4* o4 = (float4*)(out + (size_t)row * DM);
#pragma unroll
    for (int i = 0; i < 6; i++) {
        float4 wv = wo4[lane + 32 * i];
        float4 t;
        t.x = v[i].x * r2 * wv.x; t.y = v[i].y * r2 * wv.y;
        t.z = v[i].z * r2 * wv.z; t.w = v[i].w * r2 * wv.w;
        o4[lane + 32 * i] = t;
    }
}

// ---------------------------------------------------------------------------
// fp16 HMMA GEMM-NT: block 256x128, BK=32, 512 thr, warp 64x32, 4-stage.
// ---------------------------------------------------------------------------
#define BK 32
#define LDS_ROW 40
#define TILE_A_B (256 * LDS_ROW * 2)
#define TILE_B_B (128 * LDS_ROW * 2)
#define STAGE_B  (TILE_A_B + TILE_B_B)
#define NSTAGE 4
#define GEMM_SMEM (NSTAGE * STAGE_B)      // 122880

__global__ __launch_bounds__(512, 1) void k_gemm(
    const __half* __restrict__ A, const __half* __restrict__ B,
    float* __restrict__ C, int M, int N, int Kpad, int ldc, int addRes,
    int splitk, size_t zStride) {
    extern __shared__ char smem[];
    const uint32_t sBase = smem_u32(smem);

    const int tid = threadIdx.x;
    const int bm = blockIdx.y * 256, bn = blockIdx.x * 128;
    const int wid = tid >> 5, lane = tid & 31;
    const int wm = wid & 3, wn = wid >> 2;

    const int per = (Kpad / BK) / splitk;
    const int kStart = blockIdx.z * per * BK;
    if (splitk > 1) C += blockIdx.z * zStride;

    float acc[4][4][4];
#pragma unroll
    for (int i = 0; i < 4; i++)
#pragma unroll
        for (int j = 0; j < 4; j++)
#pragma unroll
            for (int q = 0; q < 4; q++) acc[i][j][q] = 0.f;

    const int lrow = tid >> 2;
    const int lc = tid & 3;
    const int okA0 = (bm + lrow) < M ? 16 : 0;
    const int okA1 = (bm + lrow + 128) < M ? 16 : 0;
    const int okB  = (bn + lrow) < N ? 16 : 0;
    const size_t gA0 = (size_t)(bm + lrow) * Kpad + lc * 8;
    const size_t gA1 = gA0 + (size_t)128 * Kpad;
    const size_t gB  = (size_t)(bn + lrow) * Kpad + lc * 8;
    const uint32_t sA0 = (uint32_t)(lrow * LDS_ROW) * 2 + lc * 16;
    const uint32_t sA1 = sA0 + 128 * LDS_ROW * 2;
    const uint32_t sB  = TILE_A_B + sA0;

#define LOAD_STAGE(it, buf) do {                                               \
    int _kc = kStart + (it) * BK;                                              \
    uint32_t _d = sBase + (buf) * STAGE_B;                                     \
    cp16(_d + sA0, A + gA0 + _kc, okA0);                                       \
    cp16(_d + sA1, A + gA1 + _kc, okA1);                                       \
    cp16(_d + sB,  B + gB  + _kc, okB);                                        \
    asm volatile("cp.async.commit_group;" ::: "memory");                       \
} while (0)

    LOAD_STAGE(0, 0);
    if (per > 1) LOAD_STAGE(1, 1);
    if (per > 2) LOAD_STAGE(2, 2);

    const int aRow0 = wm * 64 + (lane & 15);
    const int aCol0 = (lane >> 4) << 3;
    const int bRow0 = wn * 32 + ((lane >> 4) << 3) + (lane & 7);
    const int bCol0 = ((lane >> 3) & 1) << 3;

    for (int it = 0; it < per; ++it) {
        int rem = per - 1 - it;
        if (rem >= 2)
            asm volatile("cp.async.wait_group 2;" ::: "memory");
        else if (rem == 1)
            asm volatile("cp.async.wait_group 1;" ::: "memory");
        else
            asm volatile("cp.async.wait_group 0;" ::: "memory");
        __syncthreads();
        if (it + 3 < per) LOAD_STAGE(it + 3, (it + 3) % NSTAGE);

        const uint32_t pA = sBase + (it % NSTAGE) * STAGE_B;
        const uint32_t pB = pA + TILE_A_B;

#pragma unroll
        for (int k16 = 0; k16 < 2; ++k16) {
            const int ac = k16 * 16 + aCol0;
            const int bc = k16 * 16 + bCol0;
            uint32_t af[4][4];
#pragma unroll
            for (int mt = 0; mt < 4; ++mt) {
                uint32_t off = (uint32_t)((aRow0 + mt * 16) * LDS_ROW + ac) * 2;
                ldsm4(af[mt][0], af[mt][1], af[mt][2], af[mt][3], pA + off);
            }
            uint32_t bf[2][4];
#pragma unroll
            for (int g = 0; g < 2; ++g) {
                uint32_t off = (uint32_t)((bRow0 + g * 16) * LDS_ROW + bc) * 2;
                ldsm4(bf[g][0], bf[g][1], bf[g][2], bf[g][3], pB + off);
            }
#pragma unroll
            for (int mt = 0; mt < 4; ++mt)
#pragma unroll
                for (int g = 0; g < 2; ++g) {
                    mma16816(acc[mt][2 * g],     af[mt], &bf[g][0]);
                    mma16816(acc[mt][2 * g + 1], af[mt], &bf[g][2]);
                }
        }
    }

#pragma unroll
    for (int mt = 0; mt < 4; ++mt) {
#pragma unroll
        for (int h = 0; h < 2; ++h) {
            int m = bm + wm * 64 + mt * 16 + (lane >> 2) + h * 8;
            if (m >= M) continue;
#pragma unroll
            for (int nt = 0; nt < 4; ++nt) {
                int n = bn + wn * 32 + nt * 8 + (lane & 3) * 2;
                if (n < N) {
                    float2 v = make_float2(acc[mt][nt][2 * h], acc[mt][nt][2 * h + 1]);
                    float* cp = C + (size_t)m * ldc + n;
                    if (addRes) { float2 o = *(float2*)cp; v.x += o.x; v.y += o.y; }
                    *(float2*)cp = v;
                }
            }
        }
    }
#undef LOAD_STAGE
}

// ---------------------------------------------------------------------------
__global__ void k_reduce4(const float* __restrict__ p, float* __restrict__ out,
                          __half* __restrict__ dbh) {
    int idx = blockIdx.x * blockDim.x + threadIdx.x;
    if (idx >= TOTAL * 80) return;
    const size_t s = (size_t)TOTAL * 80;
    float v = (p[idx] + p[idx + s]) + (p[idx + 2 * s] + p[idx + 3 * s]);
    out[idx] = v;
    int row = idx / 80, col = idx - row * 80;
    if (col < 48) {
        dbh[(size_t)row * 64 + col] = __float2half(v);
    } else if (col < 64) {
        dbh[(size_t)row * 64 + col] = __float2half(0.f);
    }
}

// ---------------------------------------------------------------------------
// conv: scalar per (row, channel); writes fp32 xs + fp16 operand
// ---------------------------------------------------------------------------
__global__ void k_conv(const float* __restrict__ xz,
                       const float* __restrict__ cw,
                       const float* __restrict__ cb,
                       float* __restrict__ xs,
                       __half* __restrict__ xh) {
    int idx = blockIdx.x * blockDim.x + threadIdx.x;
    if (idx >= TOTAL * DI) return;
    int row = idx / DI;
    int d = idx - row * DI;
    int b = 0;
#pragma unroll
    for (int i = 1; i < NSUBJ; i++) if (row >= c_off[i]) b = i;
    int l = row - c_off[b];
    float acc = cb[d];
#pragma unroll
    for (int j = 0; j < 4; j++) {
        int ll = l - 3 + j;
        if (ll >= 0)
            acc = fmaf(cw[d * 4 + j], xz[(size_t)(row - 3 + j) * (2 * DI) + d], acc);
    }
    float v = acc * __frcp_rn(1.f + __expf(-acc));
    xs[idx] = v;
    xh[idx] = __float2half(v);
}

// ---------------------------------------------------------------------------
// Chunked scan pass A with cheap softplus (R13)
// ---------------------------------------------------------------------------
__global__ __launch_bounds__(128) void k_scanA(
    float* __restrict__ dtp, float* __restrict__ xs,
    const float* __restrict__ dbl,
    float* __restrict__ hend, float* __restrict__ schunk,
    const float* __restrict__ dtb, const float* __restrict__ alog,
    const float* __restrict__ Dp) {
    int bx = blockIdx.x;
    int s = bx / (MAXCH * 12);
    int rem = bx - s * (MAXCH * 12);
    int c = rem / 12;
    int d = (rem - c * 12) * 128 + threadIdx.x;
    int len = c_len[s];
    int t0 = c * CHUNK;
    if (t0 >= len) return;
    int tend = min(t0 + CHUNK, len);
    int off = c_off[s];

    float a[DS], st[DS];
    bool fast = true;
#pragma unroll
    for (int n = 0; n < DS; n++) {
        a[n] = -expf(alog[d * DS + n]);
        st[n] = 0.f;
        fast &= (fabsf(a[n] + (float)(n + 1)) <= 1e-5f * (float)(n + 1));
    }
    float bias = dtb[d], Dd = Dp[d];
    float S = 0.f;

    for (int t = t0; t < tend; t++) {
        size_t idx = (size_t)(off + t) * DI + d;
        float dtr = dtp[idx] + bias;
        float dt, p;
        if (dtr > 15.f) { dt = dtr; p = __expf(-dtr); }
        else {
            float e = __expf(dtr);
            p = __frcp_rn(1.f + e);          // = exp(-softplus(dtr))
            dt = __logf(1.f + e);
        }
        S += dt;
        dtp[idx] = S;
        float xt = xs[idx];
        const float4* bc = (const float4*)(dbl + (size_t)(off + t) * 80 + DTRANK);
        float Bv[DS], Cv[DS];
        *(float4*)&Bv[0]  = bc[0]; *(float4*)&Bv[4]  = bc[1];
        *(float4*)&Bv[8]  = bc[2]; *(float4*)&Bv[12] = bc[3];
        *(float4*)&Cv[0]  = bc[4]; *(float4*)&Cv[4]  = bc[5];
        *(float4*)&Cv[8]  = bc[6]; *(float4*)&Cv[12] = bc[7];
        float u = dt * xt;
        float y = 0.f;
        if (fast) {
            float dA = 1.f;
#pragma unroll
            for (int n = 0; n < DS; n++) {
                dA *= p;                     // p^(n+1) = exp(dt * a_n)
                st[n] = fmaf(dA, st[n], u * Bv[n]);
                y = fmaf(st[n], Cv[n], y);
            }
        } else {
#pragma unroll
            for (int n = 0; n < DS; n++) {
                float dA = __expf(dt * a[n]);
                st[n] = fmaf(dA, st[n], u * Bv[n]);
                y = fmaf(st[n], Cv[n], y);
            }
        }
        xs[idx] = y + xt * Dd;
    }

    size_t hb = ((size_t)(s * MAXCH + c) * DI + d) * DS;
    float4* hp = (float4*)(hend + hb);
    hp[0] = *(float4*)&st[0];  hp[1] = *(float4*)&st[4];
    hp[2] = *(float4*)&st[8];  hp[3] = *(float4*)&st[12];
    schunk[(size_t)(s * MAXCH + c) * DI + d] = S;
}

// ---------------------------------------------------------------------------
__global__ __launch_bounds__(128) void k_scanB(
    const float* __restrict__ hend, const float* __restrict__ schunk,
    float* __restrict__ hstart, const float* __restrict__ alog) {
    int bx = blockIdx.x;
    int s = bx / 12;
    int d = (bx - s * 12) * 128 + threadIdx.x;
    int nch = (c_len[s] + CHUNK - 1) / CHUNK;

    float a[DS], h[DS];
#pragma unroll
    for (int n = 0; n < DS; n++) {
        a[n] = -expf(alog[d * DS + n]);
        h[n] = 0.f;
    }

    for (int c = 0; c < nch; c++) {
        size_t hb = ((size_t)(s * MAXCH + c) * DI + d) * DS;
        float4* hs = (float4*)(hstart + hb);
        hs[0] = *(float4*)&h[0];  hs[1] = *(float4*)&h[4];
        hs[2] = *(float4*)&h[8];  hs[3] = *(float4*)&h[12];
        float Sc = schunk[(size_t)(s * MAXCH + c) * DI + d];
        const float4* he = (const float4*)(hend + hb);
        float e[DS];
        *(float4*)&e[0] = he[0];  *(float4*)&e[4]  = he[1];
        *(float4*)&e[8] = he[2];  *(float4*)&e[12] = he[3];
#pragma unroll
        for (int n = 0; n < DS; n++)
            h[n] = fmaf(__expf(Sc * a[n]), h[n], e[n]);
    }
}

// ---------------------------------------------------------------------------
__global__ __launch_bounds__(128) void k_scanC(
    const float* __restrict__ dtp, const float* __restrict__ xs,
    const float* __restrict__ dbl, const float* __restrict__ xz,
    const float* __restrict__ hstart,
    __half* __restrict__ yh,
    const float* __restrict__ alog) {
    int bx = blockIdx.x;
    int s = bx / (MAXCH * 12);
    int rem = bx - s * (MAXCH * 12);
    int c = rem / 12;
    int d = (rem - c * 12) * 128 + threadIdx.x;
    int len = c_len[s];
    int t0 = c * CHUNK;
    if (t0 >= len) return;
    int tend = min(t0 + CHUNK, len);
    int off = c_off[s];

    float a[DS], h0[DS];
    bool fast = true;
#pragma unroll
    for (int n = 0; n < DS; n++) {
        a[n] = -expf(alog[d * DS + n]);
        fast &= (fabsf(a[n] + (float)(n + 1)) <= 1e-5f * (float)(n + 1));
    }
    size_t hb = ((size_t)(s * MAXCH + c) * DI + d) * DS;
    const float4* hs = (const float4*)(hstart + hb);
    *(float4*)&h0[0] = hs[0];  *(float4*)&h0[4]  = hs[1];
    *(float4*)&h0[8] = hs[2];  *(float4*)&h0[12] = hs[3];

    for (int t = t0; t < tend; t++) {
        size_t idx = (size_t)(off + t) * DI + d;
        float S = dtp[idx];
        float y = xs[idx];
        const float4* bc = (const float4*)(dbl + (size_t)(off + t) * 80 + DTRANK + DS);
        float Cv[DS];
        *(float4*)&Cv[0] = bc[0];  *(float4*)&Cv[4]  = bc[1];
        *(float4*)&Cv[8] = bc[2];  *(float4*)&Cv[12] = bc[3];
        if (fast) {
            float q = __expf(-S);
            float w = 1.f;
#pragma unroll
            for (int n = 0; n < DS; n++) {
                w *= q;
                y = fmaf(w * h0[n], Cv[n], y);
            }
        } else {
#pragma unroll
            for (int n = 0; n < DS; n++)
                y = fmaf(__expf(S * a[n]) * h0[n], Cv[n], y);
        }
        float z = xz[(size_t)(off + t) * (2 * DI) + DI + d];
        float sig = __frcp_rn(1.f + __expf(-z));
        yh[idx] = __float2half(y * (z * sig));
    }
}

// ---------------------------------------------------------------------------
extern "C" void kernel_launch(void* const* d_in, const int* in_sizes, int n_in,
                              void* d_out, int out_size) {
    const int*   tokens     = (const int*)d_in[0];
    const float* embed      = (const float*)d_in[1];
    const float* in_norm_w  = (const float*)d_in[2];
    const float* out_norm_w = (const float*)d_in[3];
    const float* norm_w     = (const float*)d_in[4];
    const float* in_proj_w  = (const float*)d_in[5];
    const float* conv_w     = (const float*)d_in[6];
    const float* conv_b     = (const float*)d_in[7];
    const float* x_proj_w   = (const float*)d_in[8];
    const float* dt_proj_w  = (const float*)d_in[9];
    const float* dt_proj_b  = (const float*)d_in[10];
    const float* A_log      = (const float*)d_in[11];
    const float* D_param    = (const float*)d_in[12];
    const float* out_proj_w = (const float*)d_in[13];
    const float* norm_f_w   = (const float*)d_in[14];
    float* out = (float*)d_out;

    float *p_x, *p_xz, *p_xs, *p_dbl, *p_dblp, *p_op, *p_dtp, *p_he, *p_hs, *p_sc;
    __half *p_hn, *p_xsh, *p_dbh, *p_yh, *p_wip, *p_wxp, *p_wdt, *p_wop;
    cudaGetSymbolAddress((void**)&p_x,    g_x);
    cudaGetSymbolAddress((void**)&p_xz,   g_xz);
    cudaGetSymbolAddress((void**)&p_xs,   g_xs);
    cudaGetSymbolAddress((void**)&p_dbl,  g_dbl);
    cudaGetSymbolAddress((void**)&p_dblp, g_dblp);
    cudaGetSymbolAddress((void**)&p_op,   g_op);
    cudaGetSymbolAddress((void**)&p_dtp,  g_dtp);
    cudaGetSymbolAddress((void**)&p_he,   g_hend);
    cudaGetSymbolAddress((void**)&p_hs,   g_hstart);
    cudaGetSymbolAddress((void**)&p_sc,   g_schunk);
    cudaGetSymbolAddress((void**)&p_hn,   g_hn_h);
    cudaGetSymbolAddress((void**)&p_xsh,  g_xs_h);
    cudaGetSymbolAddress((void**)&p_dbh,  g_db_h);
    cudaGetSymbolAddress((void**)&p_yh,   g_y_h);
    cudaGetSymbolAddress((void**)&p_wip,  g_w_ip);
    cudaGetSymbolAddress((void**)&p_wxp,  g_w_xp);
    cudaGetSymbolAddress((void**)&p_wdt,  g_w_dt);
    cudaGetSymbolAddress((void**)&p_wop,  g_w_op);

    cudaFuncSetAttribute(k_gemm, cudaFuncAttributeMaxDynamicSharedMemorySize, GEMM_SMEM);

    const int rowBlocks = (TOTAL + 7) / 8;
    const int gy = (TOTAL + 255) / 256;          // 27
    const int scanBlocks = NSUBJ * MAXCH * 12;   // 1536

    k_cvt_all<<<(V_CVT + 255) / 256, 256>>>(in_proj_w, x_proj_w, dt_proj_w,
                                            out_proj_w, p_wip, p_wxp, p_wdt, p_wop);
    k_embed_norm<<<rowBlocks, 256>>>(tokens, embed, in_norm_w, norm_w, p_x, p_hn);

    for (int l = 0; l < 2; l++) {
        const float* cw   = conv_w    + (size_t)l * DI * 4;
        const float* cb   = conv_b    + (size_t)l * DI;
        const float* dpb  = dt_proj_b + (size_t)l * DI;
        const float* al   = A_log     + (size_t)l * DI * DS;
        const float* Dpar = D_param   + (size_t)l * DI;
        const __half* wip = p_wip + (size_t)l * 2 * DI * DM;
        const __half* wxp = p_wxp + (size_t)l * 80 * DI;
        const __half* wdt = p_wdt + (size_t)l * DI * 64;
        const __half* wop = p_wop + (size_t)l * DM * DI;

        // xz = hn @ in_proj^T : [TOTAL, 3072]
        k_gemm<<<dim3(2 * DI / 128, gy, 1), 512, GEMM_SMEM>>>(
            p_hn, wip, p_xz, TOTAL, 2 * DI, DM, 2 * DI, 0, 1, 0);

        // xs = silu(conv(x)+b) -> fp32 + fp16
        k_conv<<<(TOTAL * DI + 255) / 256, 256>>>(p_xz, cw, cb, p_xs, p_xsh);

        // dbl = xs @ x_proj^T : [TOTAL, 80] (split-K 4)
        k_gemm<<<dim3(1, gy, 4), 512, GEMM_SMEM>>>(
            p_xsh, wxp, p_dblp, TOTAL, 80, DI, 80, 0, 4, (size_t)TOTAL * 80);
        k_reduce4<<<(TOTAL * 80 + 255) / 256, 256>>>(p_dblp, p_dbl, p_dbh);

        // dtp = dbl[:, :48] @ dt_proj^T : [TOTAL, 1536] (Kpad=64)
        k_gemm<<<dim3(DI / 128, gy, 1), 512, GEMM_SMEM>>>(
            p_dbh, wdt, p_dtp, TOTAL, DI, 64, DI, 0, 1, 0);

        // chunked selective scan
        k_scanA<<<scanBlocks, 128>>>(p_dtp, p_xs, p_dbl, p_he, p_sc, dpb, al, Dpar);
        k_scanB<<<NSUBJ * 12, 128>>>(p_he, p_sc, p_hs, al);
        k_scanC<<<scanBlocks, 128>>>(p_dtp, p_xs, p_dbl, p_xz, p_hs, p_yh, al);

        // out_proj split-K=2 -> partials
        k_gemm<<<dim3(DM / 128, gy, 2), 512, GEMM_SMEM>>>(
            p_yh, wop, p_op, TOTAL, DM, DI, DM, 0, 2, (size_t)TOTAL * DM);

        if (l == 0) {
            k_reduce_op_norm<<<rowBlocks, 256>>>(p_op, p_x, norm_w + DM, p_hn);
        } else {
            k_final_fused<<<rowBlocks, 256>>>(p_op, p_x, norm_f_w, out_norm_w, out);
        }
    }
}